// round 11
// baseline (speedup 1.0000x reference)
#include <cuda_runtime.h>
#include <cuda_bf16.h>
#include <cstdint>
#include <math.h>

#define BSZ   2048
#define NTOT  4096
#define DDIM  256
#define NTILE 32
#define NTRI  528            // upper-triangular 128x128 tiles
#define BKS   64             // K per stage
#define NKT   4              // DDIM / BKS
#define STG   16384          // 128 rows * 128 B per stage buffer
#define OFF_A 0
#define OFF_B (2 * STG)
#define SMEM_TOTAL (4 * STG)
#define NORM_CTAS 256        // must be <= resident wave-1 CTAs (296)
#define L2E2  2.885390081777927f   // 2*log2(e)

// Scratch (device globals; no allocation allowed)
__device__ uint4  g_znb4[NTOT * DDIM / 8];
__device__ float  g_rowsum[NTOT];
__device__ float  g_pos[NTOT];
__device__ unsigned g_done = 0;
__device__ unsigned g_norm_done = 0;

// ---------------------------------------------------------------------------
// Helpers
// ---------------------------------------------------------------------------
__device__ __forceinline__ void cp_async16(uint32_t s, const void* g) {
    asm volatile("cp.async.cg.shared.global [%0], [%1], 16;\n" :: "r"(s), "l"(g));
}
__device__ __forceinline__ void cp_commit() { asm volatile("cp.async.commit_group;\n"); }
__device__ __forceinline__ void cp_wait1()  { asm volatile("cp.async.wait_group 1;\n"); }
__device__ __forceinline__ void cp_wait0()  { asm volatile("cp.async.wait_group 0;\n"); }
__device__ __forceinline__ void ldm_x4(uint32_t addr, uint32_t& r0, uint32_t& r1,
                                       uint32_t& r2, uint32_t& r3) {
    asm volatile("ldmatrix.sync.aligned.m8n8.x4.shared.b16 {%0,%1,%2,%3}, [%4];\n"
                 : "=r"(r0), "=r"(r1), "=r"(r2), "=r"(r3) : "r"(addr));
}
__device__ __forceinline__ void mma16816(float& d0, float& d1, float& d2, float& d3,
                                         uint32_t a0, uint32_t a1, uint32_t a2, uint32_t a3,
                                         uint32_t b0, uint32_t b1) {
    asm volatile("mma.sync.aligned.m16n8k16.row.col.f32.bf16.bf16.f32 "
                 "{%0,%1,%2,%3}, {%4,%5,%6,%7}, {%8,%9}, {%0,%1,%2,%3};\n"
                 : "+f"(d0), "+f"(d1), "+f"(d2), "+f"(d3)
                 : "r"(a0), "r"(a1), "r"(a2), "r"(a3), "r"(b0), "r"(b1));
}
__device__ __forceinline__ uint32_t sw128(uint32_t off) {
    return off ^ ((off >> 3) & 0x70);
}
__device__ __forceinline__ float ex2f(float x) {
    float r;
    asm("ex2.approx.ftz.f32 %0, %1;" : "=f"(r) : "f"(x));
    return r;
}

// ---------------------------------------------------------------------------
// Single fused kernel: normalize (first 256 CTAs) -> device-wide gate ->
// symmetric bf16 mma.sync GEMM with fused exp/rowsum epilogue -> last-CTA
// finalize + counter reset (graph-replay safe).
// ---------------------------------------------------------------------------
__global__ __launch_bounds__(256, 2) void nt_fused(const float* __restrict__ zi,
                                                   const float* __restrict__ zj,
                                                   float* __restrict__ out) {
    extern __shared__ __align__(1024) char smem[];
    uint32_t sb;
    asm("{ .reg .u64 t; cvta.to.shared.u64 t, %1; cvt.u32.u64 %0, t; }"
        : "=r"(sb) : "l"((const void*)smem));

    const int tid  = threadIdx.x;
    const int wid  = tid >> 5;
    const int lane = tid & 31;

    // ---- Phase 1: normalization by the first NORM_CTAS CTAs (16 rows each)
    if (blockIdx.x < NORM_CTAS) {
        const int rbase = blockIdx.x * 16;
#pragma unroll
        for (int it = 0; it < 2; it++) {
            int row = rbase + it * 8 + wid;        // one warp per row
            const float* src = (row < BSZ) ? (zi + (size_t)row * DDIM)
                                           : (zj + (size_t)(row - BSZ) * DDIM);
            const float4* s4 = (const float4*)src;
            float4 a = s4[lane];
            float4 b = s4[lane + 32];
            float ss = a.x*a.x + a.y*a.y + a.z*a.z + a.w*a.w
                     + b.x*b.x + b.y*b.y + b.z*b.z + b.w*b.w;
#pragma unroll
            for (int o = 16; o; o >>= 1) ss += __shfl_xor_sync(0xFFFFFFFFu, ss, o);
            float inv = 1.0f / fmaxf(sqrtf(ss), 1e-8f);
            __nv_bfloat162* d2 = (__nv_bfloat162*)((__nv_bfloat16*)g_znb4 + (size_t)row * DDIM);
            d2[2*lane]          = __nv_bfloat162(__float2bfloat16(a.x*inv), __float2bfloat16(a.y*inv));
            d2[2*lane + 1]      = __nv_bfloat162(__float2bfloat16(a.z*inv), __float2bfloat16(a.w*inv));
            d2[64 + 2*lane]     = __nv_bfloat162(__float2bfloat16(b.x*inv), __float2bfloat16(b.y*inv));
            d2[64 + 2*lane + 1] = __nv_bfloat162(__float2bfloat16(b.z*inv), __float2bfloat16(b.w*inv));
        }
        if (tid < 16) g_rowsum[rbase + tid] = 0.0f;
        __threadfence();
        __syncthreads();
        if (tid == 0) atomicAdd(&g_norm_done, 1u);
    }

    // ---- Gate: wait until all rows are normalized
    if (tid == 0) {
        unsigned v;
        do {
            asm volatile("ld.acquire.gpu.u32 %0, [%1];" : "=r"(v) : "l"(&g_norm_done));
        } while (v < NORM_CTAS);
    }
    __syncthreads();

    // ---- Phase 2: decode upper-triangular tile index -> (bi, bj), bi <= bj
    int t = blockIdx.x, bi = 0;
    while (t >= NTILE - bi) { t -= NTILE - bi; bi++; }
    const int bj = bi + t;
    const bool diag    = (bi == bj);
    const bool posTile = (bj - bi == 16);
    const int rowBase = bi * 128;
    const int colBase = bj * 128;
    const int warp_m = wid & 3;
    const int warp_n = wid >> 2;

    const __nv_bfloat16* Z = (const __nv_bfloat16*)g_znb4;

    float acc[2][8][4];
#pragma unroll
    for (int mi = 0; mi < 2; mi++)
#pragma unroll
        for (int ni = 0; ni < 8; ni++)
#pragma unroll
            for (int r = 0; r < 4; r++) acc[mi][ni][r] = 0.0f;

    // stage loader (round-8 structure); diag tiles skip the B half (B==A)
    auto load_stage = [&](int st) {
        const int buf = st & 1;
        const int nl = diag ? 4 : 8;
        for (int l = 0; l < nl; l++) {
            int ch  = tid + l * 256;
            int isB = ch >> 10;
            int idx = ch & 1023;
            int r = idx >> 3, c = idx & 7;
            uint32_t dst = sb + (isB ? OFF_B : OFF_A) + buf * STG
                         + sw128((uint32_t)(r * 128 + c * 16));
            const void* src = Z + (size_t)((isB ? colBase : rowBase) + r) * DDIM
                            + st * BKS + c * 8;
            cp_async16(dst, src);
        }
        cp_commit();
    };

    load_stage(0);

    const uint32_t bOfs = diag ? 0u : (uint32_t)OFF_B;

    for (int st = 0; st < NKT; st++) {
        if (st + 1 < NKT) { load_stage(st + 1); cp_wait1(); }
        else              { cp_wait0(); }
        __syncthreads();

        const uint32_t aBase = sb + OFF_A + (st & 1) * STG;
        const uint32_t bBase = sb + bOfs + (st & 1) * STG;
#pragma unroll
        for (int ks = 0; ks < 4; ks++) {
            uint32_t a[2][4];
#pragma unroll
            for (int mi = 0; mi < 2; mi++) {
                int r = warp_m * 32 + mi * 16 + (lane & 15);
                uint32_t ad = aBase + sw128((uint32_t)(r * 128 + ks * 32 + (lane >> 4) * 16));
                ldm_x4(ad, a[mi][0], a[mi][1], a[mi][2], a[mi][3]);
            }
            uint32_t b[8][2];
#pragma unroll
            for (int p = 0; p < 4; p++) {
                int nrow = warp_n * 64 + p * 16 + (lane >> 4) * 8 + (lane & 7);
                uint32_t ad = bBase + sw128((uint32_t)(nrow * 128 + ks * 32 + ((lane >> 3) & 1) * 16));
                uint32_t r0, r1, r2, r3;
                ldm_x4(ad, r0, r1, r2, r3);
                b[2*p][0] = r0;   b[2*p][1] = r1;
                b[2*p+1][0] = r2; b[2*p+1][1] = r3;
            }
#pragma unroll
            for (int mi = 0; mi < 2; mi++)
#pragma unroll
                for (int ni = 0; ni < 8; ni++)
                    mma16816(acc[mi][ni][0], acc[mi][ni][1], acc[mi][ni][2], acc[mi][ni][3],
                             a[mi][0], a[mi][1], a[mi][2], a[mi][3],
                             b[ni][0], b[ni][1]);
        }
        __syncthreads();
    }

    // ---- Epilogue, specialized per tile type. exp(2a-2) = ex2(fma(a,L2E2,-L2E2))
    float colsum[8][2];
#pragma unroll
    for (int ni = 0; ni < 8; ni++) { colsum[ni][0] = 0.0f; colsum[ni][1] = 0.0f; }

#pragma unroll
    for (int mi = 0; mi < 2; mi++) {
#pragma unroll
        for (int half = 0; half < 2; half++) {
            int row = rowBase + warp_m * 32 + mi * 16 + half * 8 + (lane >> 2);
            float s = 0.0f;
            if (diag) {
#pragma unroll
                for (int ni = 0; ni < 8; ni++)
#pragma unroll
                    for (int cc = 0; cc < 2; cc++) {
                        int col = colBase + warp_n * 64 + ni * 8 + 2 * (lane & 3) + cc;
                        float e = ex2f(fmaf(acc[mi][ni][half * 2 + cc], L2E2, -L2E2));
                        if (col != row) s += e;
                    }
            } else if (posTile) {
#pragma unroll
                for (int ni = 0; ni < 8; ni++)
#pragma unroll
                    for (int cc = 0; cc < 2; cc++) {
                        int col = colBase + warp_n * 64 + ni * 8 + 2 * (lane & 3) + cc;
                        float av = acc[mi][ni][half * 2 + cc];
                        if (col == row + BSZ) {
                            float v = av * 2.0f;
                            g_pos[row] = v; g_pos[col] = v;
                        }
                        float e = ex2f(fmaf(av, L2E2, -L2E2));
                        s += e;
                        colsum[ni][cc] += e;
                    }
            } else {
#pragma unroll
                for (int ni = 0; ni < 8; ni++)
#pragma unroll
                    for (int cc = 0; cc < 2; cc++) {
                        float e = ex2f(fmaf(acc[mi][ni][half * 2 + cc], L2E2, -L2E2));
                        s += e;
                        colsum[ni][cc] += e;
                    }
            }
            s += __shfl_xor_sync(0xFFFFFFFFu, s, 1);
            s += __shfl_xor_sync(0xFFFFFFFFu, s, 2);
            if ((lane & 3) == 0) atomicAdd(&g_rowsum[row], s);
        }
    }

    if (!diag) {
#pragma unroll
        for (int ni = 0; ni < 8; ni++) {
#pragma unroll
            for (int cc = 0; cc < 2; cc++) {
                float s = colsum[ni][cc];
                s += __shfl_xor_sync(0xFFFFFFFFu, s, 4);
                s += __shfl_xor_sync(0xFFFFFFFFu, s, 8);
                s += __shfl_xor_sync(0xFFFFFFFFu, s, 16);
                if (lane < 4) {
                    int col = colBase + warp_n * 64 + ni * 8 + 2 * lane + cc;
                    atomicAdd(&g_rowsum[col], s);
                }
            }
        }
    }

    // ---- last-CTA finalize + counter reset (replay-safe)
    __threadfence();
    __syncthreads();
    __shared__ unsigned s_last;
    if (tid == 0) s_last = (atomicAdd(&g_done, 1u) == NTRI - 1) ? 1u : 0u;
    __syncthreads();
    if (s_last) {
        __shared__ float red[256];
        float s = 0.0f;
        for (int i = tid; i < NTOT; i += 256)
            s += 2.0f + logf(__ldcg(&g_rowsum[i])) - __ldcg(&g_pos[i]);
        red[tid] = s;
        __syncthreads();
#pragma unroll
        for (int o = 128; o; o >>= 1) {
            if (tid < o) red[tid] += red[tid + o];
            __syncthreads();
        }
        if (tid == 0) {
            out[0] = red[0] * (1.0f / NTOT);
            // all 528 CTAs have passed both gates by definition of being last
            g_done = 0u;
            g_norm_done = 0u;
        }
    }
}

extern "C" void kernel_launch(void* const* d_in, const int* in_sizes, int n_in,
                              void* d_out, int out_size) {
    const float* zi = (const float*)d_in[0];
    const float* zj = (const float*)d_in[1];
    float* out = (float*)d_out;
    (void)in_sizes; (void)n_in; (void)out_size;

    cudaFuncSetAttribute(nt_fused, cudaFuncAttributeMaxDynamicSharedMemorySize, SMEM_TOTAL);

    nt_fused<<<NTRI, 256, SMEM_TOTAL>>>(zi, zj, out);
}

// round 12
// speedup vs baseline: 1.0635x; 1.0635x over previous
#include <cuda_runtime.h>
#include <cuda_bf16.h>
#include <cuda_fp16.h>
#include <cstdint>
#include <math.h>

#define BSZ   2048
#define NTOT  4096
#define DDIM  256
#define NTILE 32
#define NTRI  528            // upper-triangular 128x128 tiles
#define BKS   64             // K per stage
#define NKT   4              // DDIM / BKS
#define STG   16384          // 128 rows * 128 B per stage buffer
#define OFF_A 0
#define OFF_B (2 * STG)
#define SMEM_TOTAL (4 * STG)
#define L2E2  2.885390081777927f   // 2*log2(e)

// Scratch (device globals; no allocation allowed)
__device__ uint4  g_znb4[NTOT * DDIM / 8];
__device__ float  g_rowsum[NTOT];
__device__ float  g_pos[NTOT];
__device__ unsigned g_done = 0;

// ---------------------------------------------------------------------------
// Kernel 1: L2-normalize rows -> bf16; zero accumulators + completion counter
// ---------------------------------------------------------------------------
__global__ __launch_bounds__(256) void nt_normalize(const float* __restrict__ zi,
                                                    const float* __restrict__ zj) {
    int row  = (blockIdx.x * blockDim.x + threadIdx.x) >> 5;
    int lane = threadIdx.x & 31;
    if (blockIdx.x == 0 && threadIdx.x == 0) g_done = 0u;
    if (row >= NTOT) return;

    const float* src = (row < BSZ) ? (zi + (size_t)row * DDIM)
                                   : (zj + (size_t)(row - BSZ) * DDIM);
    const float4* s4 = (const float4*)src;
    float4 a = s4[lane];
    float4 b = s4[lane + 32];

    float ss = a.x*a.x + a.y*a.y + a.z*a.z + a.w*a.w
             + b.x*b.x + b.y*b.y + b.z*b.z + b.w*b.w;
#pragma unroll
    for (int o = 16; o; o >>= 1) ss += __shfl_xor_sync(0xFFFFFFFFu, ss, o);

    float inv = 1.0f / fmaxf(sqrtf(ss), 1e-8f);

    __nv_bfloat162* d2 = (__nv_bfloat162*)((__nv_bfloat16*)g_znb4 + (size_t)row * DDIM);
    d2[2*lane]          = __nv_bfloat162(__float2bfloat16(a.x*inv), __float2bfloat16(a.y*inv));
    d2[2*lane + 1]      = __nv_bfloat162(__float2bfloat16(a.z*inv), __float2bfloat16(a.w*inv));
    d2[64 + 2*lane]     = __nv_bfloat162(__float2bfloat16(b.x*inv), __float2bfloat16(b.y*inv));
    d2[64 + 2*lane + 1] = __nv_bfloat162(__float2bfloat16(b.z*inv), __float2bfloat16(b.w*inv));

    if (lane == 0) g_rowsum[row] = 0.0f;
}

// ---------------------------------------------------------------------------
// Helpers
// ---------------------------------------------------------------------------
__device__ __forceinline__ void cp_async16(uint32_t s, const void* g) {
    asm volatile("cp.async.cg.shared.global [%0], [%1], 16;\n" :: "r"(s), "l"(g));
}
__device__ __forceinline__ void cp_commit() { asm volatile("cp.async.commit_group;\n"); }
__device__ __forceinline__ void cp_wait1()  { asm volatile("cp.async.wait_group 1;\n"); }
__device__ __forceinline__ void cp_wait0()  { asm volatile("cp.async.wait_group 0;\n"); }
__device__ __forceinline__ void ldm_x4(uint32_t addr, uint32_t& r0, uint32_t& r1,
                                       uint32_t& r2, uint32_t& r3) {
    asm volatile("ldmatrix.sync.aligned.m8n8.x4.shared.b16 {%0,%1,%2,%3}, [%4];\n"
                 : "=r"(r0), "=r"(r1), "=r"(r2), "=r"(r3) : "r"(addr));
}
__device__ __forceinline__ void mma16816(float& d0, float& d1, float& d2, float& d3,
                                         uint32_t a0, uint32_t a1, uint32_t a2, uint32_t a3,
                                         uint32_t b0, uint32_t b1) {
    asm volatile("mma.sync.aligned.m16n8k16.row.col.f32.bf16.bf16.f32 "
                 "{%0,%1,%2,%3}, {%4,%5,%6,%7}, {%8,%9}, {%0,%1,%2,%3};\n"
                 : "+f"(d0), "+f"(d1), "+f"(d2), "+f"(d3)
                 : "r"(a0), "r"(a1), "r"(a2), "r"(a3), "r"(b0), "r"(b1));
}
__device__ __forceinline__ uint32_t sw128(uint32_t off) {
    return off ^ ((off >> 3) & 0x70);
}
__device__ __forceinline__ float ex2f(float x) {
    float r;
    asm("ex2.approx.ftz.f32 %0, %1;" : "=f"(r) : "f"(x));
    return r;
}
// paired fp16 exp2: ONE MUFU op for TWO exponentials
__device__ __forceinline__ __half2 h2_ex2(__half2 x) {
    uint32_t xi = *reinterpret_cast<uint32_t*>(&x);
    uint32_t ri;
    asm("ex2.approx.f16x2 %0, %1;" : "=r"(ri) : "r"(xi));
    return *reinterpret_cast<__half2*>(&ri);
}

// ---------------------------------------------------------------------------
// Kernel 2: bf16 mma.sync GEMM on upper-triangular tiles. Round-8 mainloop
// (best measured) + f16x2 MUFU-halved epilogue + last-CTA finalize.
// ---------------------------------------------------------------------------
__global__ __launch_bounds__(256, 2) void nt_mma(float* __restrict__ out) {
    extern __shared__ __align__(1024) char smem[];
    uint32_t sb;
    asm("{ .reg .u64 t; cvta.to.shared.u64 t, %1; cvt.u32.u64 %0, t; }"
        : "=r"(sb) : "l"((const void*)smem));

    // decode upper-triangular tile index -> (bi, bj), bi <= bj
    int t = blockIdx.x, bi = 0;
    while (t >= NTILE - bi) { t -= NTILE - bi; bi++; }
    const int bj = bi + t;
    const bool diag    = (bi == bj);
    const bool posTile = (bj - bi == 16);
    const int rowBase = bi * 128;
    const int colBase = bj * 128;

    const int tid  = threadIdx.x;
    const int wid  = tid >> 5;
    const int lane = tid & 31;
    const int warp_m = wid & 3;
    const int warp_n = wid >> 2;

    const __nv_bfloat16* Z = (const __nv_bfloat16*)g_znb4;

    float acc[2][8][4];
#pragma unroll
    for (int mi = 0; mi < 2; mi++)
#pragma unroll
        for (int ni = 0; ni < 8; ni++)
#pragma unroll
            for (int r = 0; r < 4; r++) acc[mi][ni][r] = 0.0f;

    // stage loader; diag tiles skip B half (B==A)
    auto load_stage = [&](int st) {
        const int buf = st & 1;
        const int nl = diag ? 4 : 8;
        for (int l = 0; l < nl; l++) {
            int ch  = tid + l * 256;
            int isB = ch >> 10;
            int idx = ch & 1023;
            int r = idx >> 3, c = idx & 7;
            uint32_t dst = sb + (isB ? OFF_B : OFF_A) + buf * STG
                         + sw128((uint32_t)(r * 128 + c * 16));
            const void* src = Z + (size_t)((isB ? colBase : rowBase) + r) * DDIM
                            + st * BKS + c * 8;
            cp_async16(dst, src);
        }
        cp_commit();
    };

    load_stage(0);
    const uint32_t bOfs = diag ? 0u : (uint32_t)OFF_B;

    for (int st = 0; st < NKT; st++) {
        if (st + 1 < NKT) { load_stage(st + 1); cp_wait1(); }
        else              { cp_wait0(); }
        __syncthreads();

        const uint32_t aBase = sb + OFF_A + (st & 1) * STG;
        const uint32_t bBase = sb + bOfs + (st & 1) * STG;
#pragma unroll
        for (int ks = 0; ks < 4; ks++) {
            uint32_t a[2][4];
#pragma unroll
            for (int mi = 0; mi < 2; mi++) {
                int r = warp_m * 32 + mi * 16 + (lane & 15);
                uint32_t ad = aBase + sw128((uint32_t)(r * 128 + ks * 32 + (lane >> 4) * 16));
                ldm_x4(ad, a[mi][0], a[mi][1], a[mi][2], a[mi][3]);
            }
            uint32_t b[8][2];
#pragma unroll
            for (int p = 0; p < 4; p++) {
                int nrow = warp_n * 64 + p * 16 + (lane >> 4) * 8 + (lane & 7);
                uint32_t ad = bBase + sw128((uint32_t)(nrow * 128 + ks * 32 + ((lane >> 3) & 1) * 16));
                uint32_t r0, r1, r2, r3;
                ldm_x4(ad, r0, r1, r2, r3);
                b[2*p][0] = r0;   b[2*p][1] = r1;
                b[2*p+1][0] = r2; b[2*p+1][1] = r3;
            }
#pragma unroll
            for (int mi = 0; mi < 2; mi++)
#pragma unroll
                for (int ni = 0; ni < 8; ni++)
                    mma16816(acc[mi][ni][0], acc[mi][ni][1], acc[mi][ni][2], acc[mi][ni][3],
                             a[mi][0], a[mi][1], a[mi][2], a[mi][3],
                             b[ni][0], b[ni][1]);
        }
        __syncthreads();
    }

    // ---- Epilogue: f16x2 paired exp (half the MUFU ops).
    // e = 2^(a*L2E2 - L2E2) = exp(2a - 2), a in [-1.01, 1.01].
    const __half2 hM = __float2half2_rn(L2E2);
    const __half2 hB = __float2half2_rn(-L2E2);
    __half2 colsum2[8];
#pragma unroll
    for (int ni = 0; ni < 8; ni++) colsum2[ni] = __float2half2_rn(0.0f);

#pragma unroll
    for (int mi = 0; mi < 2; mi++) {
#pragma unroll
        for (int half = 0; half < 2; half++) {
            int row = rowBase + warp_m * 32 + mi * 16 + half * 8 + (lane >> 2);
            __half2 e2[8];
#pragma unroll
            for (int ni = 0; ni < 8; ni++) {
                __half2 h = __floats2half2_rn(acc[mi][ni][half * 2 + 0],
                                              acc[mi][ni][half * 2 + 1]);
                e2[ni] = h2_ex2(__hfma2(h, hM, hB));
                colsum2[ni] = __hadd2(colsum2[ni], e2[ni]);
            }
            // row-sum tree over 8 half2 (16 values)
            __half2 t0 = __hadd2(__hadd2(e2[0], e2[1]), __hadd2(e2[2], e2[3]));
            __half2 t1 = __hadd2(__hadd2(e2[4], e2[5]), __hadd2(e2[6], e2[7]));
            float2 vf = __half22float2(__hadd2(t0, t1));
            float s = vf.x + vf.y;

            if (diag) {
                // subtract self-similarity term with f32 accuracy
#pragma unroll
                for (int ni = 0; ni < 8; ni++)
#pragma unroll
                    for (int cc = 0; cc < 2; cc++) {
                        int col = colBase + warp_n * 64 + ni * 8 + 2 * (lane & 3) + cc;
                        if (col == row)
                            s -= ex2f(fmaf(acc[mi][ni][half * 2 + cc], L2E2, -L2E2));
                    }
            } else if (posTile) {
#pragma unroll
                for (int ni = 0; ni < 8; ni++)
#pragma unroll
                    for (int cc = 0; cc < 2; cc++) {
                        int col = colBase + warp_n * 64 + ni * 8 + 2 * (lane & 3) + cc;
                        if (col == row + BSZ) {
                            float v = acc[mi][ni][half * 2 + cc] * 2.0f;
                            g_pos[row] = v; g_pos[col] = v;
                        }
                    }
            }
            s += __shfl_xor_sync(0xFFFFFFFFu, s, 1);
            s += __shfl_xor_sync(0xFFFFFFFFu, s, 2);
            if ((lane & 3) == 0) atomicAdd(&g_rowsum[row], s);
        }
    }

    if (!diag) {
#pragma unroll
        for (int ni = 0; ni < 8; ni++) {
            float2 cf = __half22float2(colsum2[ni]);
            float cs0 = cf.x, cs1 = cf.y;
#pragma unroll
            for (int cc = 0; cc < 2; cc++) {
                float s = cc ? cs1 : cs0;
                s += __shfl_xor_sync(0xFFFFFFFFu, s, 4);
                s += __shfl_xor_sync(0xFFFFFFFFu, s, 8);
                s += __shfl_xor_sync(0xFFFFFFFFu, s, 16);
                if (lane < 4) {
                    int col = colBase + warp_n * 64 + ni * 8 + 2 * lane + cc;
                    atomicAdd(&g_rowsum[col], s);
                }
            }
        }
    }

    // ---- last-CTA finalize
    __threadfence();
    __syncthreads();
    __shared__ unsigned s_last;
    if (tid == 0) s_last = (atomicAdd(&g_done, 1u) == NTRI - 1) ? 1u : 0u;
    __syncthreads();
    if (s_last) {
        __shared__ float red[256];
        float s = 0.0f;
        for (int i = tid; i < NTOT; i += 256)
            s += 2.0f + logf(__ldcg(&g_rowsum[i])) - __ldcg(&g_pos[i]);
        red[tid] = s;
        __syncthreads();
#pragma unroll
        for (int o = 128; o; o >>= 1) {
            if (tid < o) red[tid] += red[tid + o];
            __syncthreads();
        }
        if (tid == 0) out[0] = red[0] * (1.0f / NTOT);
    }
}

extern "C" void kernel_launch(void* const* d_in, const int* in_sizes, int n_in,
                              void* d_out, int out_size) {
    const float* zi = (const float*)d_in[0];
    const float* zj = (const float*)d_in[1];
    float* out = (float*)d_out;
    (void)in_sizes; (void)n_in; (void)out_size;

    cudaFuncSetAttribute(nt_mma, cudaFuncAttributeMaxDynamicSharedMemorySize, SMEM_TOTAL);

    nt_normalize<<<NTOT / 8, 256>>>(zi, zj);
    nt_mma<<<NTRI, 256, SMEM_TOTAL>>>(out);
}

// round 13
// speedup vs baseline: 1.1393x; 1.0713x over previous
#include <cuda_runtime.h>
#include <cuda_bf16.h>
#include <cuda_fp16.h>
#include <cstdint>
#include <math.h>

#define BSZ   2048
#define NTOT  4096
#define DDIM  256
#define NTILE 32
#define NTRI  528            // upper-triangular 128x128 tiles
#define BKS   64             // K per stage
#define NKT   4              // DDIM / BKS
#define STG   16384          // 128 rows * 128 B per stage buffer
#define OFF_A 0
#define OFF_B (2 * STG)
#define SMEM_TOTAL (4 * STG)
#define NTHR  512
#define L2E2  2.885390081777927f   // 2*log2(e)

// Scratch (device globals; no allocation allowed)
__device__ uint4  g_znb4[NTOT * DDIM / 8];
__device__ float  g_rowsum[NTOT];
__device__ float  g_pos[NTOT];
__device__ unsigned g_done = 0;

// ---------------------------------------------------------------------------
// Kernel 1: L2-normalize rows -> bf16; zero accumulators + completion counter
// ---------------------------------------------------------------------------
__global__ __launch_bounds__(256) void nt_normalize(const float* __restrict__ zi,
                                                    const float* __restrict__ zj) {
    int row  = (blockIdx.x * blockDim.x + threadIdx.x) >> 5;
    int lane = threadIdx.x & 31;
    if (blockIdx.x == 0 && threadIdx.x == 0) g_done = 0u;
    if (row >= NTOT) return;

    const float* src = (row < BSZ) ? (zi + (size_t)row * DDIM)
                                   : (zj + (size_t)(row - BSZ) * DDIM);
    const float4* s4 = (const float4*)src;
    float4 a = s4[lane];
    float4 b = s4[lane + 32];

    float ss = a.x*a.x + a.y*a.y + a.z*a.z + a.w*a.w
             + b.x*b.x + b.y*b.y + b.z*b.z + b.w*b.w;
#pragma unroll
    for (int o = 16; o; o >>= 1) ss += __shfl_xor_sync(0xFFFFFFFFu, ss, o);

    float inv = 1.0f / fmaxf(sqrtf(ss), 1e-8f);

    __nv_bfloat162* d2 = (__nv_bfloat162*)((__nv_bfloat16*)g_znb4 + (size_t)row * DDIM);
    d2[2*lane]          = __nv_bfloat162(__float2bfloat16(a.x*inv), __float2bfloat16(a.y*inv));
    d2[2*lane + 1]      = __nv_bfloat162(__float2bfloat16(a.z*inv), __float2bfloat16(a.w*inv));
    d2[64 + 2*lane]     = __nv_bfloat162(__float2bfloat16(b.x*inv), __float2bfloat16(b.y*inv));
    d2[64 + 2*lane + 1] = __nv_bfloat162(__float2bfloat16(b.z*inv), __float2bfloat16(b.w*inv));

    if (lane == 0) g_rowsum[row] = 0.0f;
}

// ---------------------------------------------------------------------------
// Helpers
// ---------------------------------------------------------------------------
__device__ __forceinline__ void cp_async16(uint32_t s, const void* g) {
    asm volatile("cp.async.cg.shared.global [%0], [%1], 16;\n" :: "r"(s), "l"(g));
}
__device__ __forceinline__ void cp_commit() { asm volatile("cp.async.commit_group;\n"); }
__device__ __forceinline__ void cp_wait1()  { asm volatile("cp.async.wait_group 1;\n"); }
__device__ __forceinline__ void cp_wait0()  { asm volatile("cp.async.wait_group 0;\n"); }
__device__ __forceinline__ void ldm_x4(uint32_t addr, uint32_t& r0, uint32_t& r1,
                                       uint32_t& r2, uint32_t& r3) {
    asm volatile("ldmatrix.sync.aligned.m8n8.x4.shared.b16 {%0,%1,%2,%3}, [%4];\n"
                 : "=r"(r0), "=r"(r1), "=r"(r2), "=r"(r3) : "r"(addr));
}
__device__ __forceinline__ void mma16816(float& d0, float& d1, float& d2, float& d3,
                                         uint32_t a0, uint32_t a1, uint32_t a2, uint32_t a3,
                                         uint32_t b0, uint32_t b1) {
    asm volatile("mma.sync.aligned.m16n8k16.row.col.f32.bf16.bf16.f32 "
                 "{%0,%1,%2,%3}, {%4,%5,%6,%7}, {%8,%9}, {%0,%1,%2,%3};\n"
                 : "+f"(d0), "+f"(d1), "+f"(d2), "+f"(d3)
                 : "r"(a0), "r"(a1), "r"(a2), "r"(a3), "r"(b0), "r"(b1));
}
__device__ __forceinline__ uint32_t sw128(uint32_t off) {
    return off ^ ((off >> 3) & 0x70);
}
__device__ __forceinline__ float ex2f(float x) {
    float r;
    asm("ex2.approx.ftz.f32 %0, %1;" : "=f"(r) : "f"(x));
    return r;
}
__device__ __forceinline__ __half2 h2_ex2(__half2 x) {
    uint32_t xi = *reinterpret_cast<uint32_t*>(&x);
    uint32_t ri;
    asm("ex2.approx.f16x2 %0, %1;" : "=r"(ri) : "r"(xi));
    return *reinterpret_cast<__half2*>(&ri);
}

// ---------------------------------------------------------------------------
// Kernel 2: bf16 mma.sync GEMM on upper-triangular tiles.
// 512 threads, 16 warps (4m x 4n), warp tile 32x32 -> 32 acc regs/thread,
// 64-reg budget, 2 CTAs/SM = 32 warps/SM for latency hiding.
// ---------------------------------------------------------------------------
__global__ __launch_bounds__(NTHR, 2) void nt_mma(float* __restrict__ out) {
    extern __shared__ __align__(1024) char smem[];
    uint32_t sb;
    asm("{ .reg .u64 t; cvta.to.shared.u64 t, %1; cvt.u32.u64 %0, t; }"
        : "=r"(sb) : "l"((const void*)smem));

    // decode upper-triangular tile index -> (bi, bj), bi <= bj
    int t = blockIdx.x, bi = 0;
    while (t >= NTILE - bi) { t -= NTILE - bi; bi++; }
    const int bj = bi + t;
    const bool diag    = (bi == bj);
    const bool posTile = (bj - bi == 16);
    const int rowBase = bi * 128;
    const int colBase = bj * 128;

    const int tid  = threadIdx.x;
    const int wid  = tid >> 5;
    const int lane = tid & 31;
    const int warp_m = wid & 3;      // 32 rows each
    const int warp_n = wid >> 2;     // 32 cols each

    const __nv_bfloat16* Z = (const __nv_bfloat16*)g_znb4;

    float acc[2][4][4];
#pragma unroll
    for (int mi = 0; mi < 2; mi++)
#pragma unroll
        for (int ni = 0; ni < 4; ni++)
#pragma unroll
            for (int r = 0; r < 4; r++) acc[mi][ni][r] = 0.0f;

    // stage loader: 2048 16B chunks (A:1024, B:1024), 4 per thread
    auto load_stage = [&](int st) {
        const int buf = st & 1;
        const int nl = diag ? 2 : 4;
        for (int l = 0; l < nl; l++) {
            int ch  = tid + l * NTHR;
            int isB = ch >> 10;
            int idx = ch & 1023;
            int r = idx >> 3, c = idx & 7;
            uint32_t dst = sb + (isB ? OFF_B : OFF_A) + buf * STG
                         + sw128((uint32_t)(r * 128 + c * 16));
            const void* src = Z + (size_t)((isB ? colBase : rowBase) + r) * DDIM
                            + st * BKS + c * 8;
            cp_async16(dst, src);
        }
        cp_commit();
    };

    load_stage(0);
    const uint32_t bOfs = diag ? 0u : (uint32_t)OFF_B;

    for (int st = 0; st < NKT; st++) {
        if (st + 1 < NKT) { load_stage(st + 1); cp_wait1(); }
        else              { cp_wait0(); }
        __syncthreads();

        const uint32_t aBase = sb + OFF_A + (st & 1) * STG;
        const uint32_t bBase = sb + bOfs + (st & 1) * STG;
#pragma unroll
        for (int ks = 0; ks < 4; ks++) {
            uint32_t a[2][4];
#pragma unroll
            for (int mi = 0; mi < 2; mi++) {
                int r = warp_m * 32 + mi * 16 + (lane & 15);
                uint32_t ad = aBase + sw128((uint32_t)(r * 128 + ks * 32 + (lane >> 4) * 16));
                ldm_x4(ad, a[mi][0], a[mi][1], a[mi][2], a[mi][3]);
            }
            uint32_t b[4][2];
#pragma unroll
            for (int p = 0; p < 2; p++) {
                int nrow = warp_n * 32 + p * 16 + (lane >> 4) * 8 + (lane & 7);
                uint32_t ad = bBase + sw128((uint32_t)(nrow * 128 + ks * 32 + ((lane >> 3) & 1) * 16));
                uint32_t r0, r1, r2, r3;
                ldm_x4(ad, r0, r1, r2, r3);
                b[2*p][0] = r0;   b[2*p][1] = r1;
                b[2*p+1][0] = r2; b[2*p+1][1] = r3;
            }
#pragma unroll
            for (int mi = 0; mi < 2; mi++)
#pragma unroll
                for (int ni = 0; ni < 4; ni++)
                    mma16816(acc[mi][ni][0], acc[mi][ni][1], acc[mi][ni][2], acc[mi][ni][3],
                             a[mi][0], a[mi][1], a[mi][2], a[mi][3],
                             b[ni][0], b[ni][1]);
        }
        __syncthreads();
    }

    // ---- Epilogue: f16x2 paired exp. e = 2^(a*L2E2 - L2E2) = exp(2a-2)
    const __half2 hM = __float2half2_rn(L2E2);
    const __half2 hB = __float2half2_rn(-L2E2);
    __half2 colsum2[4];
#pragma unroll
    for (int ni = 0; ni < 4; ni++) colsum2[ni] = __float2half2_rn(0.0f);

#pragma unroll
    for (int mi = 0; mi < 2; mi++) {
#pragma unroll
        for (int half = 0; half < 2; half++) {
            int row = rowBase + warp_m * 32 + mi * 16 + half * 8 + (lane >> 2);
            __half2 e2[4];
#pragma unroll
            for (int ni = 0; ni < 4; ni++) {
                __half2 h = __floats2half2_rn(acc[mi][ni][half * 2 + 0],
                                              acc[mi][ni][half * 2 + 1]);
                e2[ni] = h2_ex2(__hfma2(h, hM, hB));
                colsum2[ni] = __hadd2(colsum2[ni], e2[ni]);
            }
            float2 vf = __half22float2(__hadd2(__hadd2(e2[0], e2[1]),
                                               __hadd2(e2[2], e2[3])));
            float s = vf.x + vf.y;

            if (diag) {
                // subtract self-similarity term with f32 accuracy
#pragma unroll
                for (int ni = 0; ni < 4; ni++)
#pragma unroll
                    for (int cc = 0; cc < 2; cc++) {
                        int col = colBase + warp_n * 32 + ni * 8 + 2 * (lane & 3) + cc;
                        if (col == row)
                            s -= ex2f(fmaf(acc[mi][ni][half * 2 + cc], L2E2, -L2E2));
                    }
            } else if (posTile) {
#pragma unroll
                for (int ni = 0; ni < 4; ni++)
#pragma unroll
                    for (int cc = 0; cc < 2; cc++) {
                        int col = colBase + warp_n * 32 + ni * 8 + 2 * (lane & 3) + cc;
                        if (col == row + BSZ) {
                            float v = acc[mi][ni][half * 2 + cc] * 2.0f;
                            g_pos[row] = v; g_pos[col] = v;
                        }
                    }
            }
            s += __shfl_xor_sync(0xFFFFFFFFu, s, 1);
            s += __shfl_xor_sync(0xFFFFFFFFu, s, 2);
            if ((lane & 3) == 0) atomicAdd(&g_rowsum[row], s);
        }
    }

    if (!diag) {
#pragma unroll
        for (int ni = 0; ni < 4; ni++) {
            float2 cf = __half22float2(colsum2[ni]);
#pragma unroll
            for (int cc = 0; cc < 2; cc++) {
                float s = cc ? cf.y : cf.x;
                s += __shfl_xor_sync(0xFFFFFFFFu, s, 4);
                s += __shfl_xor_sync(0xFFFFFFFFu, s, 8);
                s += __shfl_xor_sync(0xFFFFFFFFu, s, 16);
                if (lane < 4) {
                    int col = colBase + warp_n * 32 + ni * 8 + 2 * lane + cc;
                    atomicAdd(&g_rowsum[col], s);
                }
            }
        }
    }

    // ---- last-CTA finalize
    __threadfence();
    __syncthreads();
    __shared__ unsigned s_last;
    if (tid == 0) s_last = (atomicAdd(&g_done, 1u) == NTRI - 1) ? 1u : 0u;
    __syncthreads();
    if (s_last) {
        __shared__ float red[NTHR];
        float s = 0.0f;
        for (int i = tid; i < NTOT; i += NTHR)
            s += 2.0f + logf(__ldcg(&g_rowsum[i])) - __ldcg(&g_pos[i]);
        red[tid] = s;
        __syncthreads();
#pragma unroll
        for (int o = NTHR / 2; o; o >>= 1) {
            if (tid < o) red[tid] += red[tid + o];
            __syncthreads();
        }
        if (tid == 0) out[0] = red[0] * (1.0f / NTOT);
    }
}

extern "C" void kernel_launch(void* const* d_in, const int* in_sizes, int n_in,
                              void* d_out, int out_size) {
    const float* zi = (const float*)d_in[0];
    const float* zj = (const float*)d_in[1];
    float* out = (float*)d_out;
    (void)in_sizes; (void)n_in; (void)out_size;

    cudaFuncSetAttribute(nt_mma, cudaFuncAttributeMaxDynamicSharedMemorySize, SMEM_TOTAL);

    nt_normalize<<<NTOT / 8, 256>>>(zi, zj);
    nt_mma<<<NTRI, NTHR, SMEM_TOTAL>>>(out);
}